// round 1
// baseline (speedup 1.0000x reference)
#include <cuda_runtime.h>
#include <math.h>

// ---------------- problem constants ----------------
#define TT 128   // seq len
#define BB 256   // batch
#define HH 512   // hidden
#define GG 2048  // 4*H gates
#define VV 128   // vocab
#define LL 128   // latent

// ---------------- device scratch (no allocations allowed) ----------------
__device__ float g_seq [TT*BB*HH];       // embedded input [T,B,H]
__device__ float g_seq1[TT*BB*2*HH];     // layer-1 input  [T,B,2H]
__device__ float g_preF[TT*BB*GG];       // precomputed x-gates, fwd dir (reused across layers)
__device__ float g_preB[TT*BB*GG];       // precomputed x-gates, bwd dir
__device__ float g_y0f [TT*BB*HH];
__device__ float g_y0b [TT*BB*HH];
__device__ float g_y1f [TT*BB*HH];
__device__ float g_y1b [TT*BB*HH];
__device__ float g_c0f [BB*HH];
__device__ float g_c0b [BB*HH];
__device__ float g_c1f [BB*HH];
__device__ float g_c1b [BB*HH];
__device__ float g_zeros[BB*HH];         // NEVER written: stays zero (load-time .bss init)
__device__ float g_z   [BB*LL];
__device__ float g_dh0 [2*BB*HH];        // decoder layer0 h ping-pong
__device__ float g_dh1 [2*BB*HH];        // decoder layer1 h ping-pong
__device__ float g_dc0 [BB*HH];
__device__ float g_dc1 [BB*HH];
__device__ int   g_tok [BB];

// ---------------- embedding gather: seq[t,b,:] = emb[x[b,t],:] ----------------
__global__ void embed_kernel(const int* __restrict__ x, const float* __restrict__ emb,
                             float* __restrict__ seq) {
    int total = TT*BB*HH;
    for (int i = blockIdx.x*blockDim.x + threadIdx.x; i < total; i += gridDim.x*blockDim.x) {
        int t = i / (BB*HH);
        int r = i % (BB*HH);
        int b = r / HH;
        int h = r % HH;
        seq[i] = emb[x[b*TT + t]*HH + h];
    }
}

// ---------------- concat: seq1[r, 0:H]=y0f[r], seq1[r, H:2H]=y0b[r] ----------------
__global__ void concat_kernel(const float* __restrict__ yf, const float* __restrict__ yb,
                              float* __restrict__ seq1) {
    int total = TT*BB*2*HH;
    for (int i = blockIdx.x*blockDim.x + threadIdx.x; i < total; i += gridDim.x*blockDim.x) {
        int r = i / (2*HH);
        int j = i % (2*HH);
        seq1[i] = (j < HH) ? yf[r*HH + j] : yb[r*HH + j - HH];
    }
}

// ---------------- generic SGEMM: C[M,N] = A[M,K] @ W[N,K]^T + bias[N] ----------------
// 64x64 tile, BK=16, 256 threads, 4x4 per thread.
#define GBM 64
#define GBN 64
#define GBK 16
__global__ __launch_bounds__(256) void sgemm_bias(const float* __restrict__ A,
                                                  const float* __restrict__ W,
                                                  const float* __restrict__ bias,
                                                  float* __restrict__ C,
                                                  int M, int N, int K) {
    __shared__ float As[GBK][GBM+1];
    __shared__ float Ws[GBK][GBN+1];
    int bm = blockIdx.y * GBM;
    int bn = blockIdx.x * GBN;
    int tid = threadIdx.x;
    int tx = tid % 16;        // 4 cols each
    int ty = tid / 16;        // 4 rows each
    float acc[4][4] = {};
    for (int k0 = 0; k0 < K; k0 += GBK) {
        #pragma unroll
        for (int i = tid; i < GBM*GBK; i += 256) {
            int m = i / GBK, k = i % GBK;
            As[k][m] = A[(size_t)(bm+m)*K + k0 + k];
        }
        #pragma unroll
        for (int i = tid; i < GBN*GBK; i += 256) {
            int n = i / GBK, k = i % GBK;
            Ws[k][n] = W[(size_t)(bn+n)*K + k0 + k];
        }
        __syncthreads();
        #pragma unroll
        for (int k = 0; k < GBK; k++) {
            float a[4], w[4];
            #pragma unroll
            for (int i = 0; i < 4; i++) a[i] = As[k][ty*4+i];
            #pragma unroll
            for (int j = 0; j < 4; j++) w[j] = Ws[k][tx*4+j];
            #pragma unroll
            for (int i = 0; i < 4; i++)
                #pragma unroll
                for (int j = 0; j < 4; j++)
                    acc[i][j] += a[i]*w[j];
        }
        __syncthreads();
    }
    #pragma unroll
    for (int i = 0; i < 4; i++) {
        int m = bm + ty*4 + i;
        #pragma unroll
        for (int j = 0; j < 4; j++) {
            int n = bn + tx*4 + j;
            C[(size_t)m*N + n] = acc[i][j] + bias[n];
        }
    }
}

// ---------------- fused LSTM recurrent step (both directions via grid.z) -------------
// gates = pre[t] + h_in @ Whh^T ; elementwise LSTM update; writes h,c.
// Tile: 64 batch rows x 32 h-cols x 4 gates. 256 threads, each 4 rows x 2 cols x 4 gates.
struct DirArgs {
    const float* pre;   // [B,4H] for this timestep (includes x-part + bias)
    const float* hin;   // [B,H]
    const float* cin;   // [B,H]
    float* cout;        // [B,H]
    float* hout;        // [B,H]
    const float* Whh;   // [4H,H]
};

#define SBM 64
#define SBN 32
#define SBK 16
__device__ __forceinline__ float sigf(float v) { return 1.0f / (1.0f + expf(-v)); }

__global__ __launch_bounds__(256) void lstm_step_kernel(DirArgs a0, DirArgs a1) {
    DirArgs d = (blockIdx.z == 0) ? a0 : a1;
    __shared__ float Hs[SBK][SBM+1];
    __shared__ float Ws[4][SBK][SBN+1];
    int bm = blockIdx.y * SBM;
    int bn = blockIdx.x * SBN;
    int tid = threadIdx.x;
    int tx = tid % 16;   // 2 cols
    int ty = tid / 16;   // 4 rows
    float acc[4][4][2] = {};
    for (int k0 = 0; k0 < HH; k0 += SBK) {
        #pragma unroll
        for (int i = tid; i < SBM*SBK; i += 256) {
            int m = i / SBK, k = i % SBK;
            Hs[k][m] = d.hin[(bm+m)*HH + k0 + k];
        }
        #pragma unroll
        for (int i = tid; i < 4*SBN*SBK; i += 256) {
            int g = i / (SBN*SBK);
            int r = i % (SBN*SBK);
            int n = r / SBK, k = r % SBK;
            Ws[g][k][n] = d.Whh[(size_t)(g*HH + bn + n)*HH + k0 + k];
        }
        __syncthreads();
        #pragma unroll
        for (int k = 0; k < SBK; k++) {
            float a[4];
            #pragma unroll
            for (int i = 0; i < 4; i++) a[i] = Hs[k][ty*4+i];
            #pragma unroll
            for (int g = 0; g < 4; g++) {
                float w0 = Ws[g][k][tx*2];
                float w1 = Ws[g][k][tx*2+1];
                #pragma unroll
                for (int i = 0; i < 4; i++) {
                    acc[g][i][0] += a[i]*w0;
                    acc[g][i][1] += a[i]*w1;
                }
            }
        }
        __syncthreads();
    }
    #pragma unroll
    for (int i = 0; i < 4; i++) {
        int b = bm + ty*4 + i;
        #pragma unroll
        for (int j = 0; j < 2; j++) {
            int n = bn + tx*2 + j;
            float gi = acc[0][i][j] + d.pre[b*GG + 0*HH + n];
            float gf = acc[1][i][j] + d.pre[b*GG + 1*HH + n];
            float gg = acc[2][i][j] + d.pre[b*GG + 2*HH + n];
            float go = acc[3][i][j] + d.pre[b*GG + 3*HH + n];
            float cn = sigf(gf) * d.cin[b*HH + n] + sigf(gi) * tanhf(gg);
            d.cout[b*HH + n] = cn;
            d.hout[b*HH + n] = sigf(go) * tanhf(cn);
        }
    }
}

// ---------------- decoder LSTM cell: gates = x@Wih^T + h@Whh^T + b --------------------
// x source: if tok != nullptr, row b of x = emb[tok[b]] (gathered inline); else xp.
__global__ __launch_bounds__(256) void lstm_cell_kernel(const float* __restrict__ xp,
                                                        const int* __restrict__ tok,
                                                        const float* __restrict__ emb,
                                                        const float* __restrict__ Wih,
                                                        const float* __restrict__ hin,
                                                        const float* __restrict__ Whh,
                                                        const float* __restrict__ bias,
                                                        const float* __restrict__ cin,
                                                        float* __restrict__ cout,
                                                        float* __restrict__ hout) {
    __shared__ float Hs[SBK][SBM+1];
    __shared__ float Ws[4][SBK][SBN+1];
    int bm = blockIdx.y * SBM;
    int bn = blockIdx.x * SBN;
    int tid = threadIdx.x;
    int tx = tid % 16;
    int ty = tid / 16;
    float acc[4][4][2] = {};
    #pragma unroll
    for (int phase = 0; phase < 2; phase++) {
        const float* Aq = (phase == 0) ? xp : hin;
        const float* Wq = (phase == 0) ? Wih : Whh;
        for (int k0 = 0; k0 < HH; k0 += SBK) {
            if (phase == 0 && tok != nullptr) {
                #pragma unroll
                for (int i = tid; i < SBM*SBK; i += 256) {
                    int m = i / SBK, k = i % SBK;
                    Hs[k][m] = emb[tok[bm+m]*HH + k0 + k];
                }
            } else {
                #pragma unroll
                for (int i = tid; i < SBM*SBK; i += 256) {
                    int m = i / SBK, k = i % SBK;
                    Hs[k][m] = Aq[(bm+m)*HH + k0 + k];
                }
            }
            #pragma unroll
            for (int i = tid; i < 4*SBN*SBK; i += 256) {
                int g = i / (SBN*SBK);
                int r = i % (SBN*SBK);
                int n = r / SBK, k = r % SBK;
                Ws[g][k][n] = Wq[(size_t)(g*HH + bn + n)*HH + k0 + k];
            }
            __syncthreads();
            #pragma unroll
            for (int k = 0; k < SBK; k++) {
                float a[4];
                #pragma unroll
                for (int i = 0; i < 4; i++) a[i] = Hs[k][ty*4+i];
                #pragma unroll
                for (int g = 0; g < 4; g++) {
                    float w0 = Ws[g][k][tx*2];
                    float w1 = Ws[g][k][tx*2+1];
                    #pragma unroll
                    for (int i = 0; i < 4; i++) {
                        acc[g][i][0] += a[i]*w0;
                        acc[g][i][1] += a[i]*w1;
                    }
                }
            }
            __syncthreads();
        }
    }
    #pragma unroll
    for (int i = 0; i < 4; i++) {
        int b = bm + ty*4 + i;
        #pragma unroll
        for (int j = 0; j < 2; j++) {
            int n = bn + tx*2 + j;
            float gi = acc[0][i][j] + bias[0*HH + n];
            float gf = acc[1][i][j] + bias[1*HH + n];
            float gg = acc[2][i][j] + bias[2*HH + n];
            float go = acc[3][i][j] + bias[3*HH + n];
            float cn = sigf(gf) * cin[b*HH + n] + sigf(gi) * tanhf(gg);
            cout[b*HH + n] = cn;
            hout[b*HH + n] = sigf(go) * tanhf(cn);
        }
    }
}

// ---------------- mu/logvar heads: [B,2H] @ W^T + b ; also stash z=mu -----------------
__global__ __launch_bounds__(256) void head_kernel(const float* __restrict__ hf,
                                                   const float* __restrict__ hb,
                                                   const float* __restrict__ Wmu,
                                                   const float* __restrict__ bmu,
                                                   const float* __restrict__ Wlv,
                                                   const float* __restrict__ blv,
                                                   float* __restrict__ out_mu,
                                                   float* __restrict__ out_lv,
                                                   float* __restrict__ zbuf) {
    int b = blockIdx.x;
    int tid = threadIdx.x;  // 256
    __shared__ float sh[2*HH];
    for (int i = tid; i < HH; i += 256) {
        sh[i]      = hf[b*HH + i];
        sh[HH + i] = hb[b*HH + i];
    }
    __syncthreads();
    const float* W;
    float acc;
    int l;
    if (tid < LL) { l = tid;      W = Wmu + (size_t)l*2*HH; acc = bmu[l]; }
    else          { l = tid - LL; W = Wlv + (size_t)l*2*HH; acc = blv[l]; }
    #pragma unroll 8
    for (int k = 0; k < 2*HH; k++) acc += sh[k]*W[k];
    if (tid < LL) { out_mu[b*LL + l] = acc; zbuf[b*LL + l] = acc; }
    else          { out_lv[b*LL + l] = acc; }
}

// ---------------- decoder init: h0=h1=z@W^T+b, c=0, tok=1 -----------------------------
__global__ __launch_bounds__(512) void dec_init_kernel(const float* __restrict__ z,
                                                       const float* __restrict__ W,
                                                       const float* __restrict__ bias,
                                                       float* __restrict__ h0,
                                                       float* __restrict__ h1,
                                                       float* __restrict__ c0,
                                                       float* __restrict__ c1,
                                                       int* __restrict__ tok) {
    int b = blockIdx.x;
    int tid = threadIdx.x;   // 512 = H
    __shared__ float sz[LL];
    if (tid < LL) sz[tid] = z[b*LL + tid];
    __syncthreads();
    float acc = bias[tid];
    const float* w = W + (size_t)tid*LL;
    #pragma unroll 8
    for (int k = 0; k < LL; k++) acc += sz[k]*w[k];
    h0[b*HH + tid] = acc;
    h1[b*HH + tid] = acc;
    c0[b*HH + tid] = 0.0f;
    c1[b*HH + tid] = 0.0f;
    if (tid == 0) tok[b] = 1;
}

// ---------------- logits + argmax (4 batch rows per block for W reuse) ----------------
__global__ __launch_bounds__(128) void logits_argmax_kernel(const float* __restrict__ h1,
                                                            const float* __restrict__ W,
                                                            const float* __restrict__ bias,
                                                            float* __restrict__ recon,
                                                            int t,
                                                            int* __restrict__ tok) {
    int v = threadIdx.x;       // 128 = V
    int b0 = blockIdx.x * 4;
    __shared__ float sh[4][HH];
    for (int i = v; i < 4*HH; i += 128) sh[i/HH][i%HH] = h1[b0*HH + i];
    __syncthreads();
    float bv = bias[v];
    float acc0 = bv, acc1 = bv, acc2 = bv, acc3 = bv;
    const float* w = W + (size_t)v*HH;
    #pragma unroll 4
    for (int k = 0; k < HH; k++) {
        float wk = w[k];
        acc0 += sh[0][k]*wk;
        acc1 += sh[1][k]*wk;
        acc2 += sh[2][k]*wk;
        acc3 += sh[3][k]*wk;
    }
    __shared__ float sv[4][128];
    __shared__ int   si[4][128];
    float accs[4] = {acc0, acc1, acc2, acc3};
    #pragma unroll
    for (int i = 0; i < 4; i++) {
        recon[(size_t)(b0+i)*TT*VV + (size_t)t*VV + v] = accs[i];
        sv[i][v] = accs[i];
        si[i][v] = v;
    }
    __syncthreads();
    for (int s = 64; s > 0; s >>= 1) {
        if (v < s) {
            #pragma unroll
            for (int i = 0; i < 4; i++) {
                float ov = sv[i][v+s]; int oi = si[i][v+s];
                if (ov > sv[i][v] || (ov == sv[i][v] && oi < si[i][v])) {
                    sv[i][v] = ov; si[i][v] = oi;
                }
            }
        }
        __syncthreads();
    }
    if (v < 4) tok[b0 + v] = si[v][0];
}

// =================================== host launcher ====================================
extern "C" void kernel_launch(void* const* d_in, const int* in_sizes, int n_in,
                              void* d_out, int out_size) {
    const int*   x           = (const int*)  d_in[0];
    const float* emb         = (const float*)d_in[1];
    const float* enc_wih_l0  = (const float*)d_in[2];   // [2,4H,H]
    const float* enc_whh_l0  = (const float*)d_in[3];   // [2,4H,H]
    const float* enc_b_l0    = (const float*)d_in[4];   // [2,4H]
    const float* enc_wih_l1  = (const float*)d_in[5];   // [2,4H,2H]
    const float* enc_whh_l1  = (const float*)d_in[6];   // [2,4H,H]
    const float* enc_b_l1    = (const float*)d_in[7];   // [2,4H]
    const float* fc_mu_w     = (const float*)d_in[8];   // [L,2H]
    const float* fc_mu_b     = (const float*)d_in[9];   // [L]
    const float* fc_lv_w     = (const float*)d_in[10];  // [L,2H]
    const float* fc_lv_b     = (const float*)d_in[11];  // [L]
    const float* dec_in_w    = (const float*)d_in[12];  // [H,L]
    const float* dec_in_b    = (const float*)d_in[13];  // [H]
    const float* dec_wih     = (const float*)d_in[14];  // [2,4H,H]
    const float* dec_whh     = (const float*)d_in[15];  // [2,4H,H]
    const float* dec_b       = (const float*)d_in[16];  // [2,4H]
    const float* dec_out_w   = (const float*)d_in[17];  // [V,H]
    const float* dec_out_b   = (const float*)d_in[18];  // [V]

    float* out       = (float*)d_out;
    float* out_recon = out;
    float* out_mu    = out + (size_t)BB*TT*VV;
    float* out_lv    = out_mu + (size_t)BB*LL;

    float *seq, *seq1, *preF, *preB, *y0f, *y0b, *y1f, *y1b;
    float *c0f, *c0b, *c1f, *c1b, *zeros, *zbuf, *dh0, *dh1, *dc0, *dc1;
    int* tokp;
    cudaGetSymbolAddress((void**)&seq,   g_seq);
    cudaGetSymbolAddress((void**)&seq1,  g_seq1);
    cudaGetSymbolAddress((void**)&preF,  g_preF);
    cudaGetSymbolAddress((void**)&preB,  g_preB);
    cudaGetSymbolAddress((void**)&y0f,   g_y0f);
    cudaGetSymbolAddress((void**)&y0b,   g_y0b);
    cudaGetSymbolAddress((void**)&y1f,   g_y1f);
    cudaGetSymbolAddress((void**)&y1b,   g_y1b);
    cudaGetSymbolAddress((void**)&c0f,   g_c0f);
    cudaGetSymbolAddress((void**)&c0b,   g_c0b);
    cudaGetSymbolAddress((void**)&c1f,   g_c1f);
    cudaGetSymbolAddress((void**)&c1b,   g_c1b);
    cudaGetSymbolAddress((void**)&zeros, g_zeros);
    cudaGetSymbolAddress((void**)&zbuf,  g_z);
    cudaGetSymbolAddress((void**)&dh0,   g_dh0);
    cudaGetSymbolAddress((void**)&dh1,   g_dh1);
    cudaGetSymbolAddress((void**)&dc0,   g_dc0);
    cudaGetSymbolAddress((void**)&dc1,   g_dc1);
    cudaGetSymbolAddress((void**)&tokp,  g_tok);

    // 1) embedding
    embed_kernel<<<4096, 256>>>(x, emb, seq);

    // 2) encoder layer 0: precompute x-side gates (both dirs), then recurrent steps
    dim3 gemmGrd(GG/GBN, (TT*BB)/GBM);
    sgemm_bias<<<gemmGrd, 256>>>(seq, enc_wih_l0,                      enc_b_l0,      preF, TT*BB, GG, HH);
    sgemm_bias<<<gemmGrd, 256>>>(seq, enc_wih_l0 + (size_t)GG*HH,      enc_b_l0 + GG, preB, TT*BB, GG, HH);

    dim3 stepGrd(HH/SBN, BB/SBM, 2);
    for (int s = 0; s < TT; s++) {
        int tf = s, tb = TT-1-s;
        DirArgs df = { preF + (size_t)tf*BB*GG,
                       (s ? y0f + (size_t)(tf-1)*BB*HH : zeros),
                       (s ? c0f : zeros), c0f,
                       y0f + (size_t)tf*BB*HH,
                       enc_whh_l0 };
        DirArgs db = { preB + (size_t)tb*BB*GG,
                       (s ? y0b + (size_t)(tb+1)*BB*HH : zeros),
                       (s ? c0b : zeros), c0b,
                       y0b + (size_t)tb*BB*HH,
                       enc_whh_l0 + (size_t)GG*HH };
        lstm_step_kernel<<<stepGrd, 256>>>(df, db);
    }

    // 3) encoder layer 1
    concat_kernel<<<4096, 256>>>(y0f, y0b, seq1);
    sgemm_bias<<<gemmGrd, 256>>>(seq1, enc_wih_l1,                     enc_b_l1,      preF, TT*BB, GG, 2*HH);
    sgemm_bias<<<gemmGrd, 256>>>(seq1, enc_wih_l1 + (size_t)GG*2*HH,   enc_b_l1 + GG, preB, TT*BB, GG, 2*HH);
    for (int s = 0; s < TT; s++) {
        int tf = s, tb = TT-1-s;
        DirArgs df = { preF + (size_t)tf*BB*GG,
                       (s ? y1f + (size_t)(tf-1)*BB*HH : zeros),
                       (s ? c1f : zeros), c1f,
                       y1f + (size_t)tf*BB*HH,
                       enc_whh_l1 };
        DirArgs db = { preB + (size_t)tb*BB*GG,
                       (s ? y1b + (size_t)(tb+1)*BB*HH : zeros),
                       (s ? c1b : zeros), c1b,
                       y1b + (size_t)tb*BB*HH,
                       enc_whh_l1 + (size_t)GG*HH };
        lstm_step_kernel<<<stepGrd, 256>>>(df, db);
    }

    // 4) heads: mu/logvar (hf = y1f[T-1], hb = y1b[0])
    head_kernel<<<BB, 256>>>(y1f + (size_t)(TT-1)*BB*HH, y1b,
                             fc_mu_w, fc_mu_b, fc_lv_w, fc_lv_b,
                             out_mu, out_lv, zbuf);

    // 5) decoder init
    dec_init_kernel<<<BB, 512>>>(zbuf, dec_in_w, dec_in_b,
                                 dh0, dh1, dc0, dc1, tokp);

    // 6) autoregressive decode
    dim3 cellGrd(HH/SBN, BB/SBM);
    for (int t = 0; t < TT; t++) {
        int p = t & 1;
        float* h0_in  = dh0 + (size_t)p*BB*HH;
        float* h0_out = dh0 + (size_t)(1-p)*BB*HH;
        float* h1_in  = dh1 + (size_t)p*BB*HH;
        float* h1_out = dh1 + (size_t)(1-p)*BB*HH;
        // cell 0: x = emb[tok]
        lstm_cell_kernel<<<cellGrd, 256>>>(nullptr, tokp, emb,
                                           dec_wih, h0_in, dec_whh, dec_b,
                                           dc0, dc0, h0_out);
        // cell 1: x = new h0
        lstm_cell_kernel<<<cellGrd, 256>>>(h0_out, nullptr, nullptr,
                                           dec_wih + (size_t)GG*HH, h1_in,
                                           dec_whh + (size_t)GG*HH, dec_b + GG,
                                           dc1, dc1, h1_out);
        // logits + argmax -> recon[:, t, :], next token
        logits_argmax_kernel<<<BB/4, 128>>>(h1_out, dec_out_w, dec_out_b,
                                            out_recon, t, tokp);
    }
}

// round 2
// speedup vs baseline: 1.7336x; 1.7336x over previous
#include <cuda_runtime.h>
#include <math.h>

// ---------------- problem constants ----------------
#define TT 128   // seq len
#define BB 256   // batch
#define HH 512   // hidden
#define GG 2048  // 4*H gates
#define VV 128   // vocab
#define LL 128   // latent

// ---------------- device scratch ----------------
__device__ float g_seq [TT*BB*HH];
__device__ float g_seq1[TT*BB*2*HH];
__device__ float g_preF[TT*BB*GG];
__device__ float g_preB[TT*BB*GG];
__device__ float g_y0f [TT*BB*HH];
__device__ float g_y0b [TT*BB*HH];
__device__ float g_y1f [TT*BB*HH];
__device__ float g_y1b [TT*BB*HH];
__device__ float g_c0f [BB*HH];
__device__ float g_c0b [BB*HH];
__device__ float g_c1f [BB*HH];
__device__ float g_c1b [BB*HH];
__device__ float g_zeros[BB*HH];     // never written -> stays zero
__device__ float g_z   [BB*LL];
__device__ float g_dh0 [BB*HH];
__device__ float g_dh1 [BB*HH];
__device__ float g_dc0 [BB*HH];
__device__ float g_dc1 [BB*HH];
__device__ float g_part0[BB*GG];     // h0@Whh0 + b0 (decoder partial)
__device__ float g_part1[BB*GG];     // h1@Whh1 + b1 (decoder partial)
__device__ int   g_tok [BB];

__device__ __forceinline__ float sigf(float v) { return 1.0f / (1.0f + expf(-v)); }

// ---------------- embedding gather ----------------
__global__ void embed_kernel(const int* __restrict__ x, const float* __restrict__ emb,
                             float* __restrict__ seq) {
    int total = TT*BB*HH;
    for (int i = blockIdx.x*blockDim.x + threadIdx.x; i < total; i += gridDim.x*blockDim.x) {
        int t = i / (BB*HH);
        int r = i % (BB*HH);
        int b = r / HH;
        int h = r % HH;
        seq[i] = emb[x[b*TT + t]*HH + h];
    }
}

// ---------------- concat ----------------
__global__ void concat_kernel(const float* __restrict__ yf, const float* __restrict__ yb,
                              float* __restrict__ seq1) {
    int total = TT*BB*2*HH;
    for (int i = blockIdx.x*blockDim.x + threadIdx.x; i < total; i += gridDim.x*blockDim.x) {
        int r = i / (2*HH);
        int j = i % (2*HH);
        seq1[i] = (j < HH) ? yf[r*HH + j] : yb[r*HH + j - HH];
    }
}

// ================= fast SGEMM: C[M,N] = A[M,K] @ W[N,K]^T + bias[N] ====================
// 128x128 block tile, BK=16, 256 threads, 8x8 per thread, float4, reg double-buffer.
#define PBM 128
#define PBN 128
#define PBK 16
#define PA_LD (PBM+4)
#define PW_LD (PBN+4)

__global__ __launch_bounds__(256) void sgemm_bias_f(const float* __restrict__ A,
                                                    const float* __restrict__ W,
                                                    const float* __restrict__ bias,
                                                    float* __restrict__ C,
                                                    int M, int N, int K) {
    __shared__ float As[PBK*PA_LD];
    __shared__ float Ws[PBK*PW_LD];
    const int bm = blockIdx.y * PBM;
    const int bn = blockIdx.x * PBN;
    const int tid = threadIdx.x;
    const int tx = tid % 16;       // 8 cols each
    const int ty = tid / 16;       // 8 rows each
    const int am = tid >> 1;       // 0..127
    const int ak = (tid & 1) * 8;  // 0 or 8

    const float* ap = A + (size_t)(bm + am)*K + ak;
    const float* wp = W + (size_t)(bn + am)*K + ak;

    float4 ra0 = *(const float4*)(ap);
    float4 ra1 = *(const float4*)(ap + 4);
    float4 rw0 = *(const float4*)(wp);
    float4 rw1 = *(const float4*)(wp + 4);

    float acc[8][8];
    #pragma unroll
    for (int i = 0; i < 8; i++)
        #pragma unroll
        for (int j = 0; j < 8; j++) acc[i][j] = 0.0f;

    for (int k0 = 0; k0 < K; k0 += PBK) {
        // store regs -> smem
        As[(ak+0)*PA_LD + am] = ra0.x; As[(ak+1)*PA_LD + am] = ra0.y;
        As[(ak+2)*PA_LD + am] = ra0.z; As[(ak+3)*PA_LD + am] = ra0.w;
        As[(ak+4)*PA_LD + am] = ra1.x; As[(ak+5)*PA_LD + am] = ra1.y;
        As[(ak+6)*PA_LD + am] = ra1.z; As[(ak+7)*PA_LD + am] = ra1.w;
        Ws[(ak+0)*PW_LD + am] = rw0.x; Ws[(ak+1)*PW_LD + am] = rw0.y;
        Ws[(ak+2)*PW_LD + am] = rw0.z; Ws[(ak+3)*PW_LD + am] = rw0.w;
        Ws[(ak+4)*PW_LD + am] = rw1.x; Ws[(ak+5)*PW_LD + am] = rw1.y;
        Ws[(ak+6)*PW_LD + am] = rw1.z; Ws[(ak+7)*PW_LD + am] = rw1.w;
        __syncthreads();

        if (k0 + PBK < K) {
            ra0 = *(const float4*)(ap + k0 + PBK);
            ra1 = *(const float4*)(ap + k0 + PBK + 4);
            rw0 = *(const float4*)(wp + k0 + PBK);
            rw1 = *(const float4*)(wp + k0 + PBK + 4);
        }

        #pragma unroll
        for (int k = 0; k < PBK; k++) {
            float a[8], w[8];
            *(float4*)&a[0] = *(const float4*)&As[k*PA_LD + ty*8];
            *(float4*)&a[4] = *(const float4*)&As[k*PA_LD + ty*8 + 4];
            *(float4*)&w[0] = *(const float4*)&Ws[k*PW_LD + tx*8];
            *(float4*)&w[4] = *(const float4*)&Ws[k*PW_LD + tx*8 + 4];
            #pragma unroll
            for (int i = 0; i < 8; i++)
                #pragma unroll
                for (int j = 0; j < 8; j++)
                    acc[i][j] += a[i]*w[j];
        }
        __syncthreads();
    }

    float4 bb0 = *(const float4*)(bias + bn + tx*8);
    float4 bb1 = *(const float4*)(bias + bn + tx*8 + 4);
    #pragma unroll
    for (int i = 0; i < 8; i++) {
        size_t row = (size_t)(bm + ty*8 + i)*N + bn + tx*8;
        float4 o0 = make_float4(acc[i][0]+bb0.x, acc[i][1]+bb0.y, acc[i][2]+bb0.z, acc[i][3]+bb0.w);
        float4 o1 = make_float4(acc[i][4]+bb1.x, acc[i][5]+bb1.y, acc[i][6]+bb1.z, acc[i][7]+bb1.w);
        *(float4*)&C[row]     = o0;
        *(float4*)&C[row + 4] = o1;
    }
}

// ============== shared 4-gate K=512 GEMM core (64 batch x 32 hcols x 4 gates) ==========
#define RBM 64
#define RBN 32
#define RBK 32
#define HS_LD (RBM+4)
#define WS_LD (RBN+4)

template<bool GATHER>
__device__ __forceinline__ void gate_gemm512(const float* __restrict__ Abase,
                                             const int* __restrict__ tok,
                                             const float* __restrict__ emb,
                                             const float* __restrict__ W,
                                             int bm, int bn,
                                             float* __restrict__ Hs,
                                             float* __restrict__ Ws,
                                             float acc[4][2][4]) {
    const int tid = threadIdx.x;
    const int tx = tid & 7;        // 4 cols each
    const int ty = tid >> 3;       // 2 rows each
    const int hm = tid >> 2;       // 0..63
    const int hk = (tid & 3) * 8;  // 0,8,16,24
    const int wr = tid >> 1;       // 0..127
    const int wk = (tid & 1) * 16; // 0 or 16
    const int wg = wr >> 5;        // gate
    const int wn = wr & 31;        // col

    const float* hp;
    if (GATHER) hp = emb + (size_t)tok[bm + hm]*HH + hk;
    else        hp = Abase + (size_t)(bm + hm)*HH + hk;
    const float* wp = W + (size_t)(wg*HH + bn + wn)*HH + wk;

    float4 ha0 = *(const float4*)(hp);
    float4 ha1 = *(const float4*)(hp + 4);
    float4 wa0 = *(const float4*)(wp);
    float4 wa1 = *(const float4*)(wp + 4);
    float4 wa2 = *(const float4*)(wp + 8);
    float4 wa3 = *(const float4*)(wp + 12);

    float* wsb = Ws + wg*RBK*WS_LD;

    for (int kt = 0; kt < HH; kt += RBK) {
        Hs[(hk+0)*HS_LD + hm] = ha0.x; Hs[(hk+1)*HS_LD + hm] = ha0.y;
        Hs[(hk+2)*HS_LD + hm] = ha0.z; Hs[(hk+3)*HS_LD + hm] = ha0.w;
        Hs[(hk+4)*HS_LD + hm] = ha1.x; Hs[(hk+5)*HS_LD + hm] = ha1.y;
        Hs[(hk+6)*HS_LD + hm] = ha1.z; Hs[(hk+7)*HS_LD + hm] = ha1.w;
        wsb[(wk+ 0)*WS_LD + wn] = wa0.x; wsb[(wk+ 1)*WS_LD + wn] = wa0.y;
        wsb[(wk+ 2)*WS_LD + wn] = wa0.z; wsb[(wk+ 3)*WS_LD + wn] = wa0.w;
        wsb[(wk+ 4)*WS_LD + wn] = wa1.x; wsb[(wk+ 5)*WS_LD + wn] = wa1.y;
        wsb[(wk+ 6)*WS_LD + wn] = wa1.z; wsb[(wk+ 7)*WS_LD + wn] = wa1.w;
        wsb[(wk+ 8)*WS_LD + wn] = wa2.x; wsb[(wk+ 9)*WS_LD + wn] = wa2.y;
        wsb[(wk+10)*WS_LD + wn] = wa2.z; wsb[(wk+11)*WS_LD + wn] = wa2.w;
        wsb[(wk+12)*WS_LD + wn] = wa3.x; wsb[(wk+13)*WS_LD + wn] = wa3.y;
        wsb[(wk+14)*WS_LD + wn] = wa3.z; wsb[(wk+15)*WS_LD + wn] = wa3.w;
        __syncthreads();

        if (kt + RBK < HH) {
            ha0 = *(const float4*)(hp + kt + RBK);
            ha1 = *(const float4*)(hp + kt + RBK + 4);
            wa0 = *(const float4*)(wp + kt + RBK);
            wa1 = *(const float4*)(wp + kt + RBK + 4);
            wa2 = *(const float4*)(wp + kt + RBK + 8);
            wa3 = *(const float4*)(wp + kt + RBK + 12);
        }

        #pragma unroll
        for (int k = 0; k < RBK; k++) {
            float2 a = *(const float2*)&Hs[k*HS_LD + ty*2];
            #pragma unroll
            for (int g = 0; g < 4; g++) {
                float4 w = *(const float4*)&Ws[(g*RBK + k)*WS_LD + tx*4];
                acc[g][0][0] += a.x*w.x; acc[g][0][1] += a.x*w.y;
                acc[g][0][2] += a.x*w.z; acc[g][0][3] += a.x*w.w;
                acc[g][1][0] += a.y*w.x; acc[g][1][1] += a.y*w.y;
                acc[g][1][2] += a.y*w.z; acc[g][1][3] += a.y*w.w;
            }
        }
        __syncthreads();
    }
}

// LSTM elementwise epilogue: gates = acc + pre[b, g*H+n]; update c,h.
__device__ __forceinline__ void lstm_epilogue(float acc[4][2][4],
                                              const float* __restrict__ pre,
                                              const float* __restrict__ cin,
                                              float* __restrict__ cout,
                                              float* __restrict__ hout,
                                              int bm, int bn) {
    const int tx = threadIdx.x & 7;
    const int ty = threadIdx.x >> 3;
    #pragma unroll
    for (int r = 0; r < 2; r++) {
        int b = bm + ty*2 + r;
        int n0 = bn + tx*4;
        const float* pb = pre + (size_t)b*GG;
        float4 pi = *(const float4*)(pb + 0*HH + n0);
        float4 pf = *(const float4*)(pb + 1*HH + n0);
        float4 pg = *(const float4*)(pb + 2*HH + n0);
        float4 po = *(const float4*)(pb + 3*HH + n0);
        float4 c4 = *(const float4*)(cin + (size_t)b*HH + n0);
        float gi[4] = {pi.x+acc[0][r][0], pi.y+acc[0][r][1], pi.z+acc[0][r][2], pi.w+acc[0][r][3]};
        float gf[4] = {pf.x+acc[1][r][0], pf.y+acc[1][r][1], pf.z+acc[1][r][2], pf.w+acc[1][r][3]};
        float gg[4] = {pg.x+acc[2][r][0], pg.y+acc[2][r][1], pg.z+acc[2][r][2], pg.w+acc[2][r][3]};
        float go[4] = {po.x+acc[3][r][0], po.y+acc[3][r][1], po.z+acc[3][r][2], po.w+acc[3][r][3]};
        float cc[4] = {c4.x, c4.y, c4.z, c4.w};
        float co[4], ho[4];
        #pragma unroll
        for (int j = 0; j < 4; j++) {
            float cn = sigf(gf[j])*cc[j] + sigf(gi[j])*tanhf(gg[j]);
            co[j] = cn;
            ho[j] = sigf(go[j])*tanhf(cn);
        }
        *(float4*)(cout + (size_t)b*HH + n0) = make_float4(co[0],co[1],co[2],co[3]);
        *(float4*)(hout + (size_t)b*HH + n0) = make_float4(ho[0],ho[1],ho[2],ho[3]);
    }
}

// ---------------- encoder recurrent step (both dirs via grid.z) ----------------
struct DirArgs {
    const float* pre;
    const float* hin;
    const float* cin;
    float* cout;
    float* hout;
    const float* Whh;
};

__global__ __launch_bounds__(256) void lstm_step2(DirArgs A0, DirArgs A1) {
    __shared__ float Hs[RBK*HS_LD];
    __shared__ float Ws[4*RBK*WS_LD];
    DirArgs d = blockIdx.z ? A1 : A0;
    int bm = blockIdx.y * RBM;
    int bn = blockIdx.x * RBN;
    float acc[4][2][4];
    #pragma unroll
    for (int g = 0; g < 4; g++)
        #pragma unroll
        for (int r = 0; r < 2; r++)
            #pragma unroll
            for (int c = 0; c < 4; c++) acc[g][r][c] = 0.0f;
    gate_gemm512<false>(d.hin, nullptr, nullptr, d.Whh, bm, bn, Hs, Ws, acc);
    lstm_epilogue(acc, d.pre, d.cin, d.cout, d.hout, bm, bn);
}

// ---------------- decoder fused step (cell via z=0, partial via z=1) ----------------
struct CellArgs {
    const float* A;        // if null -> gather emb[tok]
    const int*   tok;
    const float* W;        // Wih of this layer
    const float* partial;  // h_prev@Whh + b  (includes bias)
    float* c;              // in/out
    float* h;              // out
};
struct PartArgs {
    const float* A;        // h source
    const float* W;        // Whh
    const float* bias;     // b
    float* outp;           // [B,GG]
};

__global__ __launch_bounds__(256) void dec_step(CellArgs ca, PartArgs pa,
                                                const float* __restrict__ emb) {
    __shared__ float Hs[RBK*HS_LD];
    __shared__ float Ws[4*RBK*WS_LD];
    int bm = blockIdx.y * RBM;
    int bn = blockIdx.x * RBN;
    float acc[4][2][4];
    #pragma unroll
    for (int g = 0; g < 4; g++)
        #pragma unroll
        for (int r = 0; r < 2; r++)
            #pragma unroll
            for (int c = 0; c < 4; c++) acc[g][r][c] = 0.0f;

    if (blockIdx.z == 0) {
        if (ca.tok) gate_gemm512<true >(nullptr, ca.tok, emb, ca.W, bm, bn, Hs, Ws, acc);
        else        gate_gemm512<false>(ca.A,   nullptr, nullptr, ca.W, bm, bn, Hs, Ws, acc);
        lstm_epilogue(acc, ca.partial, ca.c, ca.c, ca.h, bm, bn);
    } else {
        gate_gemm512<false>(pa.A, nullptr, nullptr, pa.W, bm, bn, Hs, Ws, acc);
        const int tx = threadIdx.x & 7;
        const int ty = threadIdx.x >> 3;
        #pragma unroll
        for (int r = 0; r < 2; r++) {
            int b = bm + ty*2 + r;
            int n0 = bn + tx*4;
            #pragma unroll
            for (int g = 0; g < 4; g++) {
                float4 bv = *(const float4*)(pa.bias + g*HH + n0);
                float4 o = make_float4(acc[g][r][0]+bv.x, acc[g][r][1]+bv.y,
                                       acc[g][r][2]+bv.z, acc[g][r][3]+bv.w);
                *(float4*)(pa.outp + (size_t)b*GG + g*HH + n0) = o;
            }
        }
    }
}

// ---------------- mu/logvar heads ----------------
__global__ __launch_bounds__(256) void head_kernel(const float* __restrict__ hf,
                                                   const float* __restrict__ hb,
                                                   const float* __restrict__ Wmu,
                                                   const float* __restrict__ bmu,
                                                   const float* __restrict__ Wlv,
                                                   const float* __restrict__ blv,
                                                   float* __restrict__ out_mu,
                                                   float* __restrict__ out_lv,
                                                   float* __restrict__ zbuf) {
    int b = blockIdx.x;
    int tid = threadIdx.x;
    __shared__ float sh[2*HH];
    for (int i = tid; i < HH; i += 256) {
        sh[i]      = hf[b*HH + i];
        sh[HH + i] = hb[b*HH + i];
    }
    __syncthreads();
    const float* W;
    float acc;
    int l;
    if (tid < LL) { l = tid;      W = Wmu + (size_t)l*2*HH; acc = bmu[l]; }
    else          { l = tid - LL; W = Wlv + (size_t)l*2*HH; acc = blv[l]; }
    #pragma unroll 8
    for (int k = 0; k < 2*HH; k++) acc += sh[k]*W[k];
    if (tid < LL) { out_mu[b*LL + l] = acc; zbuf[b*LL + l] = acc; }
    else          { out_lv[b*LL + l] = acc; }
}

// ---------------- decoder init ----------------
__global__ __launch_bounds__(512) void dec_init_kernel(const float* __restrict__ z,
                                                       const float* __restrict__ W,
                                                       const float* __restrict__ bias,
                                                       float* __restrict__ h0,
                                                       float* __restrict__ h1,
                                                       float* __restrict__ c0,
                                                       float* __restrict__ c1,
                                                       int* __restrict__ tok) {
    int b = blockIdx.x;
    int tid = threadIdx.x;
    __shared__ float sz[LL];
    if (tid < LL) sz[tid] = z[b*LL + tid];
    __syncthreads();
    float acc = bias[tid];
    const float* w = W + (size_t)tid*LL;
    #pragma unroll 8
    for (int k = 0; k < LL; k++) acc += sz[k]*w[k];
    h0[b*HH + tid] = acc;
    h1[b*HH + tid] = acc;
    c0[b*HH + tid] = 0.0f;
    c1[b*HH + tid] = 0.0f;
    if (tid == 0) tok[b] = 1;
}

// ---------------- logits + argmax ----------------
__global__ __launch_bounds__(128) void logits_argmax_kernel(const float* __restrict__ h1,
                                                            const float* __restrict__ W,
                                                            const float* __restrict__ bias,
                                                            float* __restrict__ recon,
                                                            int t,
                                                            int* __restrict__ tok) {
    int v = threadIdx.x;
    int b0 = blockIdx.x * 4;
    __shared__ float sh[4][HH];
    for (int i = v; i < 4*HH/4; i += 128) {
        ((float4*)&sh[0][0])[i] = ((const float4*)(h1 + (size_t)b0*HH))[i];
    }
    __syncthreads();
    float bv = bias[v];
    float acc0 = bv, acc1 = bv, acc2 = bv, acc3 = bv;
    const float4* w4 = (const float4*)(W + (size_t)v*HH);
    #pragma unroll 4
    for (int k = 0; k < HH/4; k++) {
        float4 wv = w4[k];
        float4 s0 = *(const float4*)&sh[0][k*4];
        float4 s1 = *(const float4*)&sh[1][k*4];
        float4 s2 = *(const float4*)&sh[2][k*4];
        float4 s3 = *(const float4*)&sh[3][k*4];
        acc0 += s0.x*wv.x + s0.y*wv.y + s0.z*wv.z + s0.w*wv.w;
        acc1 += s1.x*wv.x + s1.y*wv.y + s1.z*wv.z + s1.w*wv.w;
        acc2 += s2.x*wv.x + s2.y*wv.y + s2.z*wv.z + s2.w*wv.w;
        acc3 += s3.x*wv.x + s3.y*wv.y + s3.z*wv.z + s3.w*wv.w;
    }
    __shared__ float sv[4][128];
    __shared__ int   si[4][128];
    float accs[4] = {acc0, acc1, acc2, acc3};
    #pragma unroll
    for (int i = 0; i < 4; i++) {
        recon[(size_t)(b0+i)*TT*VV + (size_t)t*VV + v] = accs[i];
        sv[i][v] = accs[i];
        si[i][v] = v;
    }
    __syncthreads();
    for (int s = 64; s > 0; s >>= 1) {
        if (v < s) {
            #pragma unroll
            for (int i = 0; i < 4; i++) {
                float ov = sv[i][v+s]; int oi = si[i][v+s];
                if (ov > sv[i][v] || (ov == sv[i][v] && oi < si[i][v])) {
                    sv[i][v] = ov; si[i][v] = oi;
                }
            }
        }
        __syncthreads();
    }
    if (v < 4) tok[b0 + v] = si[v][0];
}

// =================================== host launcher ====================================
extern "C" void kernel_launch(void* const* d_in, const int* in_sizes, int n_in,
                              void* d_out, int out_size) {
    const int*   x           = (const int*)  d_in[0];
    const float* emb         = (const float*)d_in[1];
    const float* enc_wih_l0  = (const float*)d_in[2];
    const float* enc_whh_l0  = (const float*)d_in[3];
    const float* enc_b_l0    = (const float*)d_in[4];
    const float* enc_wih_l1  = (const float*)d_in[5];
    const float* enc_whh_l1  = (const float*)d_in[6];
    const float* enc_b_l1    = (const float*)d_in[7];
    const float* fc_mu_w     = (const float*)d_in[8];
    const float* fc_mu_b     = (const float*)d_in[9];
    const float* fc_lv_w     = (const float*)d_in[10];
    const float* fc_lv_b     = (const float*)d_in[11];
    const float* dec_in_w    = (const float*)d_in[12];
    const float* dec_in_b    = (const float*)d_in[13];
    const float* dec_wih     = (const float*)d_in[14];
    const float* dec_whh     = (const float*)d_in[15];
    const float* dec_b       = (const float*)d_in[16];
    const float* dec_out_w   = (const float*)d_in[17];
    const float* dec_out_b   = (const float*)d_in[18];

    float* out       = (float*)d_out;
    float* out_recon = out;
    float* out_mu    = out + (size_t)BB*TT*VV;
    float* out_lv    = out_mu + (size_t)BB*LL;

    float *seq, *seq1, *preF, *preB, *y0f, *y0b, *y1f, *y1b;
    float *c0f, *c0b, *c1f, *c1b, *zeros, *zbuf, *dh0, *dh1, *dc0, *dc1;
    float *part0, *part1;
    int* tokp;
    cudaGetSymbolAddress((void**)&seq,   g_seq);
    cudaGetSymbolAddress((void**)&seq1,  g_seq1);
    cudaGetSymbolAddress((void**)&preF,  g_preF);
    cudaGetSymbolAddress((void**)&preB,  g_preB);
    cudaGetSymbolAddress((void**)&y0f,   g_y0f);
    cudaGetSymbolAddress((void**)&y0b,   g_y0b);
    cudaGetSymbolAddress((void**)&y1f,   g_y1f);
    cudaGetSymbolAddress((void**)&y1b,   g_y1b);
    cudaGetSymbolAddress((void**)&c0f,   g_c0f);
    cudaGetSymbolAddress((void**)&c0b,   g_c0b);
    cudaGetSymbolAddress((void**)&c1f,   g_c1f);
    cudaGetSymbolAddress((void**)&c1b,   g_c1b);
    cudaGetSymbolAddress((void**)&zeros, g_zeros);
    cudaGetSymbolAddress((void**)&zbuf,  g_z);
    cudaGetSymbolAddress((void**)&dh0,   g_dh0);
    cudaGetSymbolAddress((void**)&dh1,   g_dh1);
    cudaGetSymbolAddress((void**)&dc0,   g_dc0);
    cudaGetSymbolAddress((void**)&dc1,   g_dc1);
    cudaGetSymbolAddress((void**)&part0, g_part0);
    cudaGetSymbolAddress((void**)&part1, g_part1);
    cudaGetSymbolAddress((void**)&tokp,  g_tok);

    // 1) embedding
    embed_kernel<<<2048, 256>>>(x, emb, seq);

    // 2) encoder layer 0 pre-GEMMs
    dim3 preGrd(GG/PBN, (TT*BB)/PBM);
    sgemm_bias_f<<<preGrd, 256>>>(seq, enc_wih_l0,                 enc_b_l0,      preF, TT*BB, GG, HH);
    sgemm_bias_f<<<preGrd, 256>>>(seq, enc_wih_l0 + (size_t)GG*HH, enc_b_l0 + GG, preB, TT*BB, GG, HH);

    dim3 stepGrd(HH/RBN, BB/RBM, 2);
    for (int s = 0; s < TT; s++) {
        int tf = s, tb = TT-1-s;
        DirArgs df = { preF + (size_t)tf*BB*GG,
                       (s ? y0f + (size_t)(tf-1)*BB*HH : zeros),
                       (s ? c0f : zeros), c0f,
                       y0f + (size_t)tf*BB*HH,
                       enc_whh_l0 };
        DirArgs db = { preB + (size_t)tb*BB*GG,
                       (s ? y0b + (size_t)(tb+1)*BB*HH : zeros),
                       (s ? c0b : zeros), c0b,
                       y0b + (size_t)tb*BB*HH,
                       enc_whh_l0 + (size_t)GG*HH };
        lstm_step2<<<stepGrd, 256>>>(df, db);
    }

    // 3) encoder layer 1
    concat_kernel<<<2048, 256>>>(y0f, y0b, seq1);
    sgemm_bias_f<<<preGrd, 256>>>(seq1, enc_wih_l1,                   enc_b_l1,      preF, TT*BB, GG, 2*HH);
    sgemm_bias_f<<<preGrd, 256>>>(seq1, enc_wih_l1 + (size_t)GG*2*HH, enc_b_l1 + GG, preB, TT*BB, GG, 2*HH);
    for (int s = 0; s < TT; s++) {
        int tf = s, tb = TT-1-s;
        DirArgs df = { preF + (size_t)tf*BB*GG,
                       (s ? y1f + (size_t)(tf-1)*BB*HH : zeros),
                       (s ? c1f : zeros), c1f,
                       y1f + (size_t)tf*BB*HH,
                       enc_whh_l1 };
        DirArgs db = { preB + (size_t)tb*BB*GG,
                       (s ? y1b + (size_t)(tb+1)*BB*HH : zeros),
                       (s ? c1b : zeros), c1b,
                       y1b + (size_t)tb*BB*HH,
                       enc_whh_l1 + (size_t)GG*HH };
        lstm_step2<<<stepGrd, 256>>>(df, db);
    }

    // 4) heads
    head_kernel<<<BB, 256>>>(y1f + (size_t)(TT-1)*BB*HH, y1b,
                             fc_mu_w, fc_mu_b, fc_lv_w, fc_lv_b,
                             out_mu, out_lv, zbuf);

    // 5) decoder init + initial partial0 = h0_init@Whh0 + b0
    dec_init_kernel<<<BB, 512>>>(zbuf, dec_in_w, dec_in_b, dh0, dh1, dc0, dc1, tokp);
    sgemm_bias_f<<<dim3(GG/PBN, BB/PBM), 256>>>(dh0, dec_whh, dec_b, part0, BB, GG, HH);

    // 6) autoregressive decode with partial pipelining
    dim3 decGrd(HH/RBN, BB/RBM, 2);
    for (int t = 0; t < TT; t++) {
        // launch 1: cell0 (gates = emb[tok]@Wih0 + part0) || part1 = h1_prev@Whh1 + b1
        CellArgs c0 = { nullptr, tokp, dec_wih, part0, dc0, dh0 };
        PartArgs p1 = { dh1, dec_whh + (size_t)GG*HH, dec_b + GG, part1 };
        dec_step<<<decGrd, 256>>>(c0, p1, emb);
        // launch 2: cell1 (gates = h0@Wih1 + part1) || part0 = h0@Whh0 + b0 (for t+1)
        CellArgs c1 = { dh0, nullptr, dec_wih + (size_t)GG*HH, part1, dc1, dh1 };
        PartArgs p0 = { dh0, dec_whh, dec_b, part0 };
        dec_step<<<decGrd, 256>>>(c1, p0, emb);
        // launch 3: logits + argmax
        logits_argmax_kernel<<<BB/4, 128>>>(dh1, dec_out_w, dec_out_b, out_recon, t, tokp);
    }
}

// round 3
// speedup vs baseline: 1.8888x; 1.0895x over previous
#include <cuda_runtime.h>
#include <math.h>

// ---------------- problem constants ----------------
#define TT 128   // seq len
#define BB 256   // batch
#define HH 512   // hidden
#define GG 2048  // 4*H gates
#define VV 128   // vocab
#define LL 128   // latent

typedef unsigned long long u64t;

// f32x2 packed helpers (sm_100+ PTX; FFMA2 in SASS — 2x fp32 throughput)
__device__ __forceinline__ u64t pack2(float x, float y) {
    u64t r; asm("mov.b64 %0, {%1, %2};" : "=l"(r) : "f"(x), "f"(y)); return r;
}
__device__ __forceinline__ void fma2(u64t& d, u64t a, u64t b) {
    asm("fma.rn.f32x2 %0, %1, %2, %0;" : "+l"(d) : "l"(a), "l"(b));
}
__device__ __forceinline__ float2 unpack2(u64t v) {
    float2 r; asm("mov.b64 {%0, %1}, %2;" : "=f"(r.x), "=f"(r.y) : "l"(v)); return r;
}

// ---------------- device scratch ----------------
__device__ float g_seq [TT*BB*HH];
__device__ float g_seq1[TT*BB*2*HH];
__device__ float g_preF[TT*BB*GG];
__device__ float g_preB[TT*BB*GG];
__device__ float g_y0f [TT*BB*HH];
__device__ float g_y0b [TT*BB*HH];
__device__ float g_y1f [TT*BB*HH];
__device__ float g_y1b [TT*BB*HH];
__device__ float g_c0f [BB*HH];
__device__ float g_c0b [BB*HH];
__device__ float g_c1f [BB*HH];
__device__ float g_c1b [BB*HH];
__device__ float g_zeros[BB*HH];     // never written -> stays zero
__device__ float g_z   [BB*LL];
__device__ float g_dh0 [BB*HH];
__device__ float g_dh1 [BB*HH];
__device__ float g_dc0 [BB*HH];
__device__ float g_dc1 [BB*HH];
__device__ float g_part0[BB*GG];
__device__ float g_part1[BB*GG];
__device__ int   g_tok [BB];

__device__ __forceinline__ float sigf(float v) { return 1.0f / (1.0f + expf(-v)); }

// ---------------- embedding gather ----------------
__global__ void embed_kernel(const int* __restrict__ x, const float* __restrict__ emb,
                             float* __restrict__ seq) {
    int total = TT*BB*HH;
    for (int i = blockIdx.x*blockDim.x + threadIdx.x; i < total; i += gridDim.x*blockDim.x) {
        int t = i / (BB*HH);
        int r = i % (BB*HH);
        int b = r / HH;
        int h = r % HH;
        seq[i] = emb[x[b*TT + t]*HH + h];
    }
}

// ---------------- concat ----------------
__global__ void concat_kernel(const float* __restrict__ yf, const float* __restrict__ yb,
                              float* __restrict__ seq1) {
    int total = TT*BB*2*HH;
    for (int i = blockIdx.x*blockDim.x + threadIdx.x; i < total; i += gridDim.x*blockDim.x) {
        int r = i / (2*HH);
        int j = i % (2*HH);
        seq1[i] = (j < HH) ? yf[r*HH + j] : yb[r*HH + j - HH];
    }
}

// ================= SGEMM (f32x2): C[M,N] = A[M,K] @ W[N,K]^T + bias[N] =================
// 128x128 tile, BK=16, 256 threads, per-thread 8 rows(4 pairs) x 8 cols, FFMA2.
#define PBM 128
#define PBN 128
#define PBK 16
#define PA_LD 132
#define PW_LD 132

__global__ __launch_bounds__(256) void sgemm_bias_f(const float* __restrict__ A,
                                                    const float* __restrict__ W,
                                                    const float* __restrict__ bias,
                                                    float* __restrict__ C,
                                                    int M, int N, int K) {
    __shared__ __align__(16) float As[PBK*PA_LD];
    __shared__ __align__(16) float Ws[PBK*PW_LD];
    const int bm = blockIdx.y * PBM;
    const int bn = blockIdx.x * PBN;
    const int tid = threadIdx.x;
    const int tx = tid % 16;       // 8 cols each
    const int ty = tid / 16;       // 8 rows each (4 pairs)
    const int am = tid >> 1;       // 0..127
    const int ak = (tid & 1) * 8;  // 0 or 8

    const float* ap = A + (size_t)(bm + am)*K + ak;
    const float* wp = W + (size_t)(bn + am)*K + ak;

    float4 ra0 = *(const float4*)(ap);
    float4 ra1 = *(const float4*)(ap + 4);
    float4 rw0 = *(const float4*)(wp);
    float4 rw1 = *(const float4*)(wp + 4);

    u64t acc2[4][8];
    #pragma unroll
    for (int p = 0; p < 4; p++)
        #pragma unroll
        for (int j = 0; j < 8; j++) acc2[p][j] = 0ull;

    for (int k0 = 0; k0 < K; k0 += PBK) {
        As[(ak+0)*PA_LD + am] = ra0.x; As[(ak+1)*PA_LD + am] = ra0.y;
        As[(ak+2)*PA_LD + am] = ra0.z; As[(ak+3)*PA_LD + am] = ra0.w;
        As[(ak+4)*PA_LD + am] = ra1.x; As[(ak+5)*PA_LD + am] = ra1.y;
        As[(ak+6)*PA_LD + am] = ra1.z; As[(ak+7)*PA_LD + am] = ra1.w;
        Ws[(ak+0)*PW_LD + am] = rw0.x; Ws[(ak+1)*PW_LD + am] = rw0.y;
        Ws[(ak+2)*PW_LD + am] = rw0.z; Ws[(ak+3)*PW_LD + am] = rw0.w;
        Ws[(ak+4)*PW_LD + am] = rw1.x; Ws[(ak+5)*PW_LD + am] = rw1.y;
        Ws[(ak+6)*PW_LD + am] = rw1.z; Ws[(ak+7)*PW_LD + am] = rw1.w;
        __syncthreads();

        if (k0 + PBK < K) {
            ra0 = *(const float4*)(ap + k0 + PBK);
            ra1 = *(const float4*)(ap + k0 + PBK + 4);
            rw0 = *(const float4*)(wp + k0 + PBK);
            rw1 = *(const float4*)(wp + k0 + PBK + 4);
        }

        #pragma unroll
        for (int k = 0; k < PBK; k++) {
            // A row-pairs: natural 64-bit loads from [k][m] tile
            ulonglong2 A0 = *(const ulonglong2*)&As[k*PA_LD + ty*8];
            ulonglong2 A1 = *(const ulonglong2*)&As[k*PA_LD + ty*8 + 4];
            u64t apair[4] = {A0.x, A0.y, A1.x, A1.y};
            float w[8];
            *(float4*)&w[0] = *(const float4*)&Ws[k*PW_LD + tx*8];
            *(float4*)&w[4] = *(const float4*)&Ws[k*PW_LD + tx*8 + 4];
            #pragma unroll
            for (int j = 0; j < 8; j++) {
                u64t w2 = pack2(w[j], w[j]);
                #pragma unroll
                for (int p = 0; p < 4; p++) fma2(acc2[p][j], apair[p], w2);
            }
        }
        __syncthreads();
    }

    float bb[8];
    *(float4*)&bb[0] = *(const float4*)(bias + bn + tx*8);
    *(float4*)&bb[4] = *(const float4*)(bias + bn + tx*8 + 4);
    #pragma unroll
    for (int p = 0; p < 4; p++) {
        float2 v[8];
        #pragma unroll
        for (int j = 0; j < 8; j++) v[j] = unpack2(acc2[p][j]);
        #pragma unroll
        for (int sub = 0; sub < 2; sub++) {
            size_t row = (size_t)(bm + ty*8 + 2*p + sub)*N + bn + tx*8;
            float o[8];
            #pragma unroll
            for (int j = 0; j < 8; j++) o[j] = (sub ? v[j].y : v[j].x) + bb[j];
            *(float4*)&C[row]     = *(float4*)&o[0];
            *(float4*)&C[row + 4] = *(float4*)&o[4];
        }
    }
}

// ============== 4-gate K=512 GEMM core (64 batch x 32 hcols x 4 gates, f32x2) ==========
// 256 threads: tx = col (0..31), ty = row-octet (0..7). Per thread: 8 rows(4 pairs) x 1 col x 4 gates.
#define RBM 64
#define RBN 32
#define RBK 32
#define HS_LD 68
#define WS_LD 33

template<bool GATHER>
__device__ __forceinline__ void gate_gemm512(const float* __restrict__ Abase,
                                             const int* __restrict__ tok,
                                             const float* __restrict__ emb,
                                             const float* __restrict__ W,
                                             int bm, int bn,
                                             float* __restrict__ Hs,
                                             float* __restrict__ Ws,
                                             u64t acc2[4][4]) {
    const int tid = threadIdx.x;
    const int tx = tid & 31;
    const int ty = tid >> 5;
    const int hm = tid >> 2;       // 0..63
    const int hk = (tid & 3) * 8;  // 0,8,16,24
    const int wr = tid >> 1;       // 0..127
    const int wk = (tid & 1) * 16; // 0 or 16
    const int wg = wr >> 5;        // gate
    const int wn = wr & 31;        // col

    const float* hp;
    if (GATHER) hp = emb + (size_t)tok[bm + hm]*HH + hk;
    else        hp = Abase + (size_t)(bm + hm)*HH + hk;
    const float* wp = W + (size_t)(wg*HH + bn + wn)*HH + wk;

    float4 ha0 = *(const float4*)(hp);
    float4 ha1 = *(const float4*)(hp + 4);
    float4 wa0 = *(const float4*)(wp);
    float4 wa1 = *(const float4*)(wp + 4);
    float4 wa2 = *(const float4*)(wp + 8);
    float4 wa3 = *(const float4*)(wp + 12);

    for (int kt = 0; kt < HH; kt += RBK) {
        Hs[(hk+0)*HS_LD + hm] = ha0.x; Hs[(hk+1)*HS_LD + hm] = ha0.y;
        Hs[(hk+2)*HS_LD + hm] = ha0.z; Hs[(hk+3)*HS_LD + hm] = ha0.w;
        Hs[(hk+4)*HS_LD + hm] = ha1.x; Hs[(hk+5)*HS_LD + hm] = ha1.y;
        Hs[(hk+6)*HS_LD + hm] = ha1.z; Hs[(hk+7)*HS_LD + hm] = ha1.w;
        Ws[(wg*RBK + wk+ 0)*WS_LD + wn] = wa0.x; Ws[(wg*RBK + wk+ 1)*WS_LD + wn] = wa0.y;
        Ws[(wg*RBK + wk+ 2)*WS_LD + wn] = wa0.z; Ws[(wg*RBK + wk+ 3)*WS_LD + wn] = wa0.w;
        Ws[(wg*RBK + wk+ 4)*WS_LD + wn] = wa1.x; Ws[(wg*RBK + wk+ 5)*WS_LD + wn] = wa1.y;
        Ws[(wg*RBK + wk+ 6)*WS_LD + wn] = wa1.z; Ws[(wg*RBK + wk+ 7)*WS_LD + wn] = wa1.w;
        Ws[(wg*RBK + wk+ 8)*WS_LD + wn] = wa2.x; Ws[(wg*RBK + wk+ 9)*WS_LD + wn] = wa2.y;
        Ws[(wg*RBK + wk+10)*WS_LD + wn] = wa2.z; Ws[(wg*RBK + wk+11)*WS_LD + wn] = wa2.w;
        Ws[(wg*RBK + wk+12)*WS_LD + wn] = wa3.x; Ws[(wg*RBK + wk+13)*WS_LD + wn] = wa3.y;
        Ws[(wg*RBK + wk+14)*WS_LD + wn] = wa3.z; Ws[(wg*RBK + wk+15)*WS_LD + wn] = wa3.w;
        __syncthreads();

        if (kt + RBK < HH) {
            ha0 = *(const float4*)(hp + kt + RBK);
            ha1 = *(const float4*)(hp + kt + RBK + 4);
            wa0 = *(const float4*)(wp + kt + RBK);
            wa1 = *(const float4*)(wp + kt + RBK + 4);
            wa2 = *(const float4*)(wp + kt + RBK + 8);
            wa3 = *(const float4*)(wp + kt + RBK + 12);
        }

        #pragma unroll 8
        for (int k = 0; k < RBK; k++) {
            // A row-pairs: natural 64-bit broadcast loads
            ulonglong2 A0 = *(const ulonglong2*)&Hs[k*HS_LD + ty*8];
            ulonglong2 A1 = *(const ulonglong2*)&Hs[k*HS_LD + ty*8 + 4];
            u64t apair[4] = {A0.x, A0.y, A1.x, A1.y};
            #pragma unroll
            for (int g = 0; g < 4; g++) {
                float w = Ws[(g*RBK + k)*WS_LD + tx];
                u64t w2 = pack2(w, w);
                #pragma unroll
                for (int p = 0; p < 4; p++) fma2(acc2[g][p], apair[p], w2);
            }
        }
        __syncthreads();
    }
}

// LSTM elementwise epilogue
__device__ __forceinline__ void lstm_epilogue(u64t acc2[4][4],
                                              const float* __restrict__ pre,
                                              const float* __restrict__ cin,
                                              float* __restrict__ cout,
                                              float* __restrict__ hout,
                                              int bm, int bn) {
    const int tx = threadIdx.x & 31;
    const int ty = threadIdx.x >> 5;
    const int n = bn + tx;
    #pragma unroll
    for (int p = 0; p < 4; p++) {
        float2 vi = unpack2(acc2[0][p]);
        float2 vf = unpack2(acc2[1][p]);
        float2 vg = unpack2(acc2[2][p]);
        float2 vo = unpack2(acc2[3][p]);
        #pragma unroll
        for (int sub = 0; sub < 2; sub++) {
            int b = bm + ty*8 + 2*p + sub;
            const float* pb = pre + (size_t)b*GG;
            float gi = pb[0*HH + n] + (sub ? vi.y : vi.x);
            float gf = pb[1*HH + n] + (sub ? vf.y : vf.x);
            float gg = pb[2*HH + n] + (sub ? vg.y : vg.x);
            float go = pb[3*HH + n] + (sub ? vo.y : vo.x);
            float cn = sigf(gf)*cin[(size_t)b*HH + n] + sigf(gi)*tanhf(gg);
            cout[(size_t)b*HH + n] = cn;
            hout[(size_t)b*HH + n] = sigf(go)*tanhf(cn);
        }
    }
}

// ---------------- encoder recurrent step (both dirs via grid.z) ----------------
struct DirArgs {
    const float* pre;
    const float* hin;
    const float* cin;
    float* cout;
    float* hout;
    const float* Whh;
};

__global__ __launch_bounds__(256) void lstm_step2(DirArgs A0, DirArgs A1) {
    __shared__ __align__(16) float Hs[RBK*HS_LD];
    __shared__ __align__(16) float Ws[4*RBK*WS_LD];
    DirArgs d = blockIdx.z ? A1 : A0;
    int bm = blockIdx.y * RBM;
    int bn = blockIdx.x * RBN;
    u64t acc2[4][4];
    #pragma unroll
    for (int g = 0; g < 4; g++)
        #pragma unroll
        for (int p = 0; p < 4; p++) acc2[g][p] = 0ull;
    gate_gemm512<false>(d.hin, nullptr, nullptr, d.Whh, bm, bn, Hs, Ws, acc2);
    lstm_epilogue(acc2, d.pre, d.cin, d.cout, d.hout, bm, bn);
}

// ---------------- decoder fused step (cell via z=0, partial via z=1) ----------------
struct CellArgs {
    const float* A;
    const int*   tok;
    const float* W;
    const float* partial;
    float* c;
    float* h;
};
struct PartArgs {
    const float* A;
    const float* W;
    const float* bias;
    float* outp;
};

__global__ __launch_bounds__(256) void dec_step(CellArgs ca, PartArgs pa,
                                                const float* __restrict__ emb) {
    __shared__ __align__(16) float Hs[RBK*HS_LD];
    __shared__ __align__(16) float Ws[4*RBK*WS_LD];
    int bm = blockIdx.y * RBM;
    int bn = blockIdx.x * RBN;
    u64t acc2[4][4];
    #pragma unroll
    for (int g = 0; g < 4; g++)
        #pragma unroll
        for (int p = 0; p < 4; p++) acc2[g][p] = 0ull;

    if (blockIdx.z == 0) {
        if (ca.tok) gate_gemm512<true >(nullptr, ca.tok, emb, ca.W, bm, bn, Hs, Ws, acc2);
        else        gate_gemm512<false>(ca.A,   nullptr, nullptr, ca.W, bm, bn, Hs, Ws, acc2);
        lstm_epilogue(acc2, ca.partial, ca.c, ca.c, ca.h, bm, bn);
    } else {
        gate_gemm512<false>(pa.A, nullptr, nullptr, pa.W, bm, bn, Hs, Ws, acc2);
        const int tx = threadIdx.x & 31;
        const int ty = threadIdx.x >> 5;
        const int n = bn + tx;
        #pragma unroll
        for (int g = 0; g < 4; g++) {
            float bv = pa.bias[g*HH + n];
            #pragma unroll
            for (int p = 0; p < 4; p++) {
                float2 v = unpack2(acc2[g][p]);
                int b0 = bm + ty*8 + 2*p;
                pa.outp[(size_t)(b0+0)*GG + g*HH + n] = v.x + bv;
                pa.outp[(size_t)(b0+1)*GG + g*HH + n] = v.y + bv;
            }
        }
    }
}

// ---------------- mu/logvar heads ----------------
__global__ __launch_bounds__(256) void head_kernel(const float* __restrict__ hf,
                                                   const float* __restrict__ hb,
                                                   const float* __restrict__ Wmu,
                                                   const float* __restrict__ bmu,
                                                   const float* __restrict__ Wlv,
                                                   const float* __restrict__ blv,
                                                   float* __restrict__ out_mu,
                                                   float* __restrict__ out_lv,
                                                   float* __restrict__ zbuf) {
    int b = blockIdx.x;
    int tid = threadIdx.x;
    __shared__ float sh[2*HH];
    for (int i = tid; i < HH; i += 256) {
        sh[i]      = hf[b*HH + i];
        sh[HH + i] = hb[b*HH + i];
    }
    __syncthreads();
    const float* W;
    float acc;
    int l;
    if (tid < LL) { l = tid;      W = Wmu + (size_t)l*2*HH; acc = bmu[l]; }
    else          { l = tid - LL; W = Wlv + (size_t)l*2*HH; acc = blv[l]; }
    #pragma unroll 8
    for (int k = 0; k < 2*HH; k++) acc += sh[k]*W[k];
    if (tid < LL) { out_mu[b*LL + l] = acc; zbuf[b*LL + l] = acc; }
    else          { out_lv[b*LL + l] = acc; }
}

// ---------------- decoder init ----------------
__global__ __launch_bounds__(512) void dec_init_kernel(const float* __restrict__ z,
                                                       const float* __restrict__ W,
                                                       const float* __restrict__ bias,
                                                       float* __restrict__ h0,
                                                       float* __restrict__ h1,
                                                       float* __restrict__ c0,
                                                       float* __restrict__ c1,
                                                       int* __restrict__ tok) {
    int b = blockIdx.x;
    int tid = threadIdx.x;
    __shared__ float sz[LL];
    if (tid < LL) sz[tid] = z[b*LL + tid];
    __syncthreads();
    float acc = bias[tid];
    const float* w = W + (size_t)tid*LL;
    #pragma unroll 8
    for (int k = 0; k < LL; k++) acc += sz[k]*w[k];
    h0[b*HH + tid] = acc;
    h1[b*HH + tid] = acc;
    c0[b*HH + tid] = 0.0f;
    c1[b*HH + tid] = 0.0f;
    if (tid == 0) tok[b] = 1;
}

// ---------------- logits + argmax ----------------
__global__ __launch_bounds__(128) void logits_argmax_kernel(const float* __restrict__ h1,
                                                            const float* __restrict__ W,
                                                            const float* __restrict__ bias,
                                                            float* __restrict__ recon,
                                                            int t,
                                                            int* __restrict__ tok) {
    int v = threadIdx.x;
    int b0 = blockIdx.x * 4;
    __shared__ float sh[4][HH];
    for (int i = v; i < 4*HH/4; i += 128) {
        ((float4*)&sh[0][0])[i] = ((const float4*)(h1 + (size_t)b0*HH))[i];
    }
    __syncthreads();
    float bv = bias[v];
    float acc0 = bv, acc1 = bv, acc2 = bv, acc3 = bv;
    const float4* w4 = (const float4*)(W + (size_t)v*HH);
    #pragma unroll 4
    for (int k = 0; k < HH/4; k++) {
        float4 wv = w4[k];
        float4 s0 = *(const float4*)&sh[0][k*4];
        float4 s1 = *(const float4*)&sh[1][k*4];
        float4 s2 = *(const float4*)&sh[2][k*4];
        float4 s3 = *(const float4*)&sh[3][k*4];
        acc0 += s0.x*wv.x + s0.y*wv.y + s0.z*wv.z + s0.w*wv.w;
        acc1 += s1.x*wv.x + s1.y*wv.y + s1.z*wv.z + s1.w*wv.w;
        acc2 += s2.x*wv.x + s2.y*wv.y + s2.z*wv.z + s2.w*wv.w;
        acc3 += s3.x*wv.x + s3.y*wv.y + s3.z*wv.z + s3.w*wv.w;
    }
    __shared__ float sv[4][128];
    __shared__ int   si[4][128];
    float accs[4] = {acc0, acc1, acc2, acc3};
    #pragma unroll
    for (int i = 0; i < 4; i++) {
        recon[(size_t)(b0+i)*TT*VV + (size_t)t*VV + v] = accs[i];
        sv[i][v] = accs[i];
        si[i][v] = v;
    }
    __syncthreads();
    for (int s = 64; s > 0; s >>= 1) {
        if (v < s) {
            #pragma unroll
            for (int i = 0; i < 4; i++) {
                float ov = sv[i][v+s]; int oi = si[i][v+s];
                if (ov > sv[i][v] || (ov == sv[i][v] && oi < si[i][v])) {
                    sv[i][v] = ov; si[i][v] = oi;
                }
            }
        }
        __syncthreads();
    }
    if (v < 4) tok[b0 + v] = si[v][0];
}

// =================================== host launcher ====================================
extern "C" void kernel_launch(void* const* d_in, const int* in_sizes, int n_in,
                              void* d_out, int out_size) {
    const int*   x           = (const int*)  d_in[0];
    const float* emb         = (const float*)d_in[1];
    const float* enc_wih_l0  = (const float*)d_in[2];
    const float* enc_whh_l0  = (const float*)d_in[3];
    const float* enc_b_l0    = (const float*)d_in[4];
    const float* enc_wih_l1  = (const float*)d_in[5];
    const float* enc_whh_l1  = (const float*)d_in[6];
    const float* enc_b_l1    = (const float*)d_in[7];
    const float* fc_mu_w     = (const float*)d_in[8];
    const float* fc_mu_b     = (const float*)d_in[9];
    const float* fc_lv_w     = (const float*)d_in[10];
    const float* fc_lv_b     = (const float*)d_in[11];
    const float* dec_in_w    = (const float*)d_in[12];
    const float* dec_in_b    = (const float*)d_in[13];
    const float* dec_wih     = (const float*)d_in[14];
    const float* dec_whh     = (const float*)d_in[15];
    const float* dec_b       = (const float*)d_in[16];
    const float* dec_out_w   = (const float*)d_in[17];
    const float* dec_out_b   = (const float*)d_in[18];

    float* out       = (float*)d_out;
    float* out_recon = out;
    float* out_mu    = out + (size_t)BB*TT*VV;
    float* out_lv    = out_mu + (size_t)BB*LL;

    float *seq, *seq1, *preF, *preB, *y0f, *y0b, *y1f, *y1b;
    float *c0f, *c0b, *c1f, *c1b, *zeros, *zbuf, *dh0, *dh1, *dc0, *dc1;
    float *part0, *part1;
    int* tokp;
    cudaGetSymbolAddress((void**)&seq,   g_seq);
    cudaGetSymbolAddress((void**)&seq1,  g_seq1);
    cudaGetSymbolAddress((void**)&preF,  g_preF);
    cudaGetSymbolAddress((void**)&preB,  g_preB);
    cudaGetSymbolAddress((void**)&y0f,   g_y0f);
    cudaGetSymbolAddress((void**)&y0b,   g_y0b);
    cudaGetSymbolAddress((void**)&y1f,   g_y1f);
    cudaGetSymbolAddress((void**)&y1b,   g_y1b);
    cudaGetSymbolAddress((void**)&c0f,   g_c0f);
    cudaGetSymbolAddress((void**)&c0b,   g_c0b);
    cudaGetSymbolAddress((void**)&c1f,   g_c1f);
    cudaGetSymbolAddress((void**)&c1b,   g_c1b);
    cudaGetSymbolAddress((void**)&zeros, g_zeros);
    cudaGetSymbolAddress((void**)&zbuf,  g_z);
    cudaGetSymbolAddress((void**)&dh0,   g_dh0);
    cudaGetSymbolAddress((void**)&dh1,   g_dh1);
    cudaGetSymbolAddress((void**)&dc0,   g_dc0);
    cudaGetSymbolAddress((void**)&dc1,   g_dc1);
    cudaGetSymbolAddress((void**)&part0, g_part0);
    cudaGetSymbolAddress((void**)&part1, g_part1);
    cudaGetSymbolAddress((void**)&tokp,  g_tok);

    // 1) embedding
    embed_kernel<<<2048, 256>>>(x, emb, seq);

    // 2) encoder layer 0 pre-GEMMs
    dim3 preGrd(GG/PBN, (TT*BB)/PBM);
    sgemm_bias_f<<<preGrd, 256>>>(seq, enc_wih_l0,                 enc_b_l0,      preF, TT*BB, GG, HH);
    sgemm_bias_f<<<preGrd, 256>>>(seq, enc_wih_l0 + (size_t)GG*HH, enc_b_l0 + GG, preB, TT*BB, GG, HH);

    dim3 stepGrd(HH/RBN, BB/RBM, 2);
    for (int s = 0; s < TT; s++) {
        int tf = s, tb = TT-1-s;
        DirArgs df = { preF + (size_t)tf*BB*GG,
                       (s ? y0f + (size_t)(tf-1)*BB*HH : zeros),
                       (s ? c0f : zeros), c0f,
                       y0f + (size_t)tf*BB*HH,
                       enc_whh_l0 };
        DirArgs db = { preB + (size_t)tb*BB*GG,
                       (s ? y0b + (size_t)(tb+1)*BB*HH : zeros),
                       (s ? c0b : zeros), c0b,
                       y0b + (size_t)tb*BB*HH,
                       enc_whh_l0 + (size_t)GG*HH };
        lstm_step2<<<stepGrd, 256>>>(df, db);
    }

    // 3) encoder layer 1
    concat_kernel<<<2048, 256>>>(y0f, y0b, seq1);
    sgemm_bias_f<<<preGrd, 256>>>(seq1, enc_wih_l1,                   enc_b_l1,      preF, TT*BB, GG, 2*HH);
    sgemm_bias_f<<<preGrd, 256>>>(seq1, enc_wih_l1 + (size_t)GG*2*HH, enc_b_l1 + GG, preB, TT*BB, GG, 2*HH);
    for (int s = 0; s < TT; s++) {
        int tf = s, tb = TT-1-s;
        DirArgs df = { preF + (size_t)tf*BB*GG,
                       (s ? y1f + (size_t)(tf-1)*BB*HH : zeros),
                       (s ? c1f : zeros), c1f,
                       y1f + (size_t)tf*BB*HH,
                       enc_whh_l1 };
        DirArgs db = { preB + (size_t)tb*BB*GG,
                       (s ? y1b + (size_t)(tb+1)*BB*HH : zeros),
                       (s ? c1b : zeros), c1b,
                       y1b + (size_t)tb*BB*HH,
                       enc_whh_l1 + (size_t)GG*HH };
        lstm_step2<<<stepGrd, 256>>>(df, db);
    }

    // 4) heads
    head_kernel<<<BB, 256>>>(y1f + (size_t)(TT-1)*BB*HH, y1b,
                             fc_mu_w, fc_mu_b, fc_lv_w, fc_lv_b,
                             out_mu, out_lv, zbuf);

    // 5) decoder init + initial partial0
    dec_init_kernel<<<BB, 512>>>(zbuf, dec_in_w, dec_in_b, dh0, dh1, dc0, dc1, tokp);
    sgemm_bias_f<<<dim3(GG/PBN, BB/PBM), 256>>>(dh0, dec_whh, dec_b, part0, BB, GG, HH);

    // 6) autoregressive decode with partial pipelining
    dim3 decGrd(HH/RBN, BB/RBM, 2);
    for (int t = 0; t < TT; t++) {
        CellArgs c0 = { nullptr, tokp, dec_wih, part0, dc0, dh0 };
        PartArgs p1 = { dh1, dec_whh + (size_t)GG*HH, dec_b + GG, part1 };
        dec_step<<<decGrd, 256>>>(c0, p1, emb);
        CellArgs c1 = { dh0, nullptr, dec_wih + (size_t)GG*HH, part1, dc1, dh1 };
        PartArgs p0 = { dh0, dec_whh, dec_b, part0 };
        dec_step<<<decGrd, 256>>>(c1, p0, emb);
        logits_argmax_kernel<<<BB/4, 128>>>(dh1, dec_out_w, dec_out_b, out_recon, t, tokp);
    }
}